// round 1
// baseline (speedup 1.0000x reference)
#include <cuda_runtime.h>

// out[b,i,n] = sum_j w[i,j] * x[b,j,n]
// x: [256, 3, 65536] fp32, w: [3,3] fp32, out: [256, 3, 65536] fp32
//
// Pure streaming kernel: each thread handles one float4 (4 columns) of one
// batch element: 3 vector loads (rows j=0,1,2), 9 FMAs per lane, 3 vector
// stores. HBM-bound; target ~384 MiB total traffic.

static constexpr int N_COLS   = 65536;
static constexpr int N4       = N_COLS / 4;   // 16384 float4 per row
static constexpr int BATCH    = 256;
static constexpr long TOTAL4  = (long)BATCH * N4;  // 4,194,304 threads

__global__ __launch_bounds__(256) void rot3_kernel(
    const float4* __restrict__ x,
    const float*  __restrict__ w,
    float4* __restrict__ out)
{
    long idx = (long)blockIdx.x * blockDim.x + threadIdx.x;
    if (idx >= TOTAL4) return;

    int b = (int)(idx >> 14);        // idx / N4
    int n = (int)(idx & (N4 - 1));   // idx % N4

    // Broadcast weight loads — same address across warp, L1-resident.
    float w00 = __ldg(w + 0), w01 = __ldg(w + 1), w02 = __ldg(w + 2);
    float w10 = __ldg(w + 3), w11 = __ldg(w + 4), w12 = __ldg(w + 5);
    float w20 = __ldg(w + 6), w21 = __ldg(w + 7), w22 = __ldg(w + 8);

    const float4* xb = x + (size_t)b * 3 * N4;
    float4 x0 = __ldg(xb + n);
    float4 x1 = __ldg(xb + N4 + n);
    float4 x2 = __ldg(xb + 2 * N4 + n);

    float4 o0, o1, o2;
    o0.x = w00 * x0.x + w01 * x1.x + w02 * x2.x;
    o0.y = w00 * x0.y + w01 * x1.y + w02 * x2.y;
    o0.z = w00 * x0.z + w01 * x1.z + w02 * x2.z;
    o0.w = w00 * x0.w + w01 * x1.w + w02 * x2.w;

    o1.x = w10 * x0.x + w11 * x1.x + w12 * x2.x;
    o1.y = w10 * x0.y + w11 * x1.y + w12 * x2.y;
    o1.z = w10 * x0.z + w11 * x1.z + w12 * x2.z;
    o1.w = w10 * x0.w + w11 * x1.w + w12 * x2.w;

    o2.x = w20 * x0.x + w21 * x1.x + w22 * x2.x;
    o2.y = w20 * x0.y + w21 * x1.y + w22 * x2.y;
    o2.z = w20 * x0.z + w21 * x1.z + w22 * x2.z;
    o2.w = w20 * x0.w + w21 * x1.w + w22 * x2.w;

    float4* ob = out + (size_t)b * 3 * N4;
    ob[n]          = o0;
    ob[N4 + n]     = o1;
    ob[2 * N4 + n] = o2;
}

extern "C" void kernel_launch(void* const* d_in, const int* in_sizes, int n_in,
                              void* d_out, int out_size)
{
    const float4* x = (const float4*)d_in[0];
    const float*  w = (const float*)d_in[1];
    float4* out = (float4*)d_out;

    const int threads = 256;
    const long blocks = (TOTAL4 + threads - 1) / threads;  // 16384 blocks
    rot3_kernel<<<(int)blocks, threads>>>(x, w, out);
}